// round 14
// baseline (speedup 1.0000x reference)
#include <cuda_runtime.h>
#include <cstdint>

// PSRoIAlign: feat [B=4, C=784, H=80, W=80] fp32, rois [512,5] fp32
// out [512, 16, 7, 7] fp32.
//
// R11: plane-stationary inversion.  The gather formulation is pinned to the
// divergent-LDG L1tex wavefront floor (~1.8M line-visits @ ~2 cyc).  Instead:
//   K1: bucket ROIs by batch image into compacted __device__ lists.
//   K2: one CTA per (b,c) plane; cp.async.bulk streams the 25.6KB plane
//       GMEM->SMEM (TMA path, no L1tex wavefronts, no STS), then each
//       matching ROI's single output for this plane is 16 LDS.32 + bilinear.
// Floor moves to LTS streaming: 80MB @ ~6300 B/cyc ~= 7.3us.

#define B_    4
#define CO_   16
#define PH_   7
#define PW_   7
#define H_    80
#define W_    80
#define C_    (CO_ * PH_ * PW_)     // 784
#define HW_   (H_ * W_)             // 6400
#define NROI  512
#define NPLANE (B_ * C_)            // 3136
#define PLANE_BYTES (HW_ * 4)       // 25600
#define TPB   128

__device__ float4 g_params[B_ * NROI];  // compacted {x1,y1,x2,y2} per batch
__device__ int    g_nidx[B_ * NROI];    // compacted roi index
__device__ int    g_cnt[B_];

// ---------------- K1: bucket ROIs by batch ----------------
__global__ void bucket_rois_kernel(const float* __restrict__ rois)
{
    __shared__ int scnt[B_];
    const int t = threadIdx.x;
    if (t < B_) scnt[t] = 0;
    __syncthreads();
    if (t < NROI) {
        const float* r = rois + t * 5;
        const int b = (int)r[0];
        float4 p = make_float4(r[1], r[2], r[3], r[4]);
        int pos = atomicAdd(&scnt[b], 1);
        g_params[b * NROI + pos] = p;
        g_nidx[b * NROI + pos]   = t;
    }
    __syncthreads();
    if (t < B_) g_cnt[t] = scnt[t];
}

// ---------------- K2: plane-stationary PSRoIAlign ----------------
__global__ __launch_bounds__(TPB, 8)
void psroi_plane_kernel(const float* __restrict__ feat,
                        float* __restrict__ out)
{
    __shared__ __align__(128) float plane[HW_];
    __shared__ __align__(8) uint64_t mbar;

    const int pidx = blockIdx.x;          // 0..3135
    const int b    = pidx / C_;
    const int c    = pidx - b * C_;       // co*49 + i*7 + j
    const int bin  = c % (PH_ * PW_);
    const int j    = bin % PW_;
    const int i    = bin / PW_;
    const int tid  = threadIdx.x;

    const uint32_t mb = (uint32_t)__cvta_generic_to_shared(&mbar);
    const uint32_t dst = (uint32_t)__cvta_generic_to_shared(plane);

    if (tid == 0) {
        asm volatile("mbarrier.init.shared.b64 [%0], %1;" :: "r"(mb), "r"(1));
    }
    __syncthreads();
    if (tid == 0) {
        asm volatile("mbarrier.arrive.expect_tx.shared.b64 _, [%0], %1;"
                     :: "r"(mb), "r"(PLANE_BYTES));
        asm volatile(
            "cp.async.bulk.shared::cta.global.mbarrier::complete_tx::bytes "
            "[%0], [%1], %2, [%3];"
            :: "r"(dst), "l"(feat + (size_t)pidx * HW_), "r"(PLANE_BYTES), "r"(mb)
            : "memory");
    }

    const int len = g_cnt[b];

    // wait for the bulk copy (parity 0)
    {
        uint32_t done;
        asm volatile(
            "{\n\t.reg .pred p;\n\t"
            "mbarrier.try_wait.parity.shared.b64 p, [%1], %2;\n\t"
            "selp.b32 %0, 1, 0, p;\n\t}"
            : "=r"(done) : "r"(mb), "r"(0) : "memory");
        while (!done) {
            asm volatile(
                "{\n\t.reg .pred p;\n\t"
                "mbarrier.try_wait.parity.shared.b64 p, [%1], %2;\n\t"
                "selp.b32 %0, 1, 0, p;\n\t}"
                : "=r"(done) : "r"(mb), "r"(0) : "memory");
        }
    }
    __syncthreads();

    for (int k = tid; k < len; k += TPB) {
        const float4 p = __ldg(&g_params[b * NROI + k]);
        const int    n = __ldg(&g_nidx[b * NROI + k]);

        const float x1 = p.x * (float)W_;
        const float y1 = p.y * (float)H_;
        const float x2 = p.z * (float)W_;
        const float y2 = p.w * (float)H_;

        const float bin_h = fmaxf(y2 - y1, 0.1f) * (1.0f / (float)PH_);
        const float bin_w = fmaxf(x2 - x1, 0.1f) * (1.0f / (float)PW_);

        int   y0i[2], y1i[2], x0i[2], x1i[2];
        float hy[2], ly[2], hx[2], lx[2];

        #pragma unroll
        for (int s = 0; s < 2; s++) {
            float ys = y1 + (float)i * bin_h + ((float)s + 0.5f) * bin_h * 0.5f;
            bool ym = (ys >= -1.0f) && (ys <= (float)H_);
            float yc = fminf(fmaxf(ys, 0.0f), (float)(H_ - 1));
            float yf = floorf(yc);
            y0i[s] = (int)yf;
            y1i[s] = min(y0i[s] + 1, H_ - 1);
            ly[s]  = ym ? (yc - yf) : 0.0f;
            hy[s]  = ym ? (1.0f - (yc - yf)) : 0.0f;

            float xs = x1 + (float)j * bin_w + ((float)s + 0.5f) * bin_w * 0.5f;
            bool xm = (xs >= -1.0f) && (xs <= (float)W_);
            float xc = fminf(fmaxf(xs, 0.0f), (float)(W_ - 1));
            float xf = floorf(xc);
            x0i[s] = (int)xf;
            x1i[s] = min(x0i[s] + 1, W_ - 1);
            lx[s]  = xm ? (xc - xf) : 0.0f;
            hx[s]  = xm ? (1.0f - (xc - xf)) : 0.0f;
        }

        float sum = 0.0f;
        #pragma unroll
        for (int sy = 0; sy < 2; sy++) {
            const int r0 = y0i[sy] * W_;
            const int r1 = y1i[sy] * W_;
            #pragma unroll
            for (int sx = 0; sx < 2; sx++) {
                const float v00 = plane[r0 + x0i[sx]];
                const float v01 = plane[r0 + x1i[sx]];
                const float v10 = plane[r1 + x0i[sx]];
                const float v11 = plane[r1 + x1i[sx]];
                sum += hy[sy] * (hx[sx] * v00 + lx[sx] * v01)
                     + ly[sy] * (hx[sx] * v10 + lx[sx] * v11);
            }
        }

        out[(size_t)n * C_ + c] = sum * 0.25f;
    }
}

extern "C" void kernel_launch(void* const* d_in, const int* in_sizes, int n_in,
                              void* d_out, int out_size)
{
    const float* feat = (const float*)d_in[0];
    const float* rois = (const float*)d_in[1];
    float* out        = (float*)d_out;

    bucket_rois_kernel<<<1, NROI>>>(rois);
    psroi_plane_kernel<<<NPLANE, TPB>>>(feat, out);
}